// round 1
// baseline (speedup 1.0000x reference)
#include <cuda_runtime.h>
#include <math.h>

// Problem constants (fixed by the reference)
#define NN 50000
#define DH 128
#define EE 600000

// ---------------- scratch (static device allocations are allowed) ------------
__device__ float g_x[NN * DH];     // node features after head / after each layer
__device__ float g_agg[NN * DH];   // neighbor aggregation buffer
__device__ float g_h[NN * DH];     // GIN MLP hidden
__device__ float g_z[NN];          // tail output
__device__ float g_stats[2];       // mu, rstd

// ---------------- GEMM: [M x K] * [K x 128] + bias (+relu), A may be x+agg ---
// BM=64, BN=128, BK=32, 256 threads, each thread computes an 8x4 microtile.
template <bool RELU, bool ADD>
__global__ void __launch_bounds__(256, 2)
gemm_k(const float* __restrict__ A, const float* __restrict__ A2,
       const float* __restrict__ W, const float* __restrict__ bias,
       float* __restrict__ out, int M, int K)
{
    constexpr int BM = 64;
    constexpr int BK = 32;

    __shared__ float As[BK][BM + 4];   // K-major, padded: float4 reads stay aligned
    __shared__ float Bs[BK][128];

    const int tid  = threadIdx.x;
    const int tcol = tid & 31;         // covers cols 4*tcol .. 4*tcol+3
    const int trow = tid >> 5;         // covers rows 8*trow .. 8*trow+7
    const int rowBase = blockIdx.x * BM;

    float acc[8][4];
#pragma unroll
    for (int i = 0; i < 8; i++)
#pragma unroll
        for (int j = 0; j < 4; j++) acc[i][j] = 0.f;

    for (int k0 = 0; k0 < K; k0 += BK) {
        // ---- load A tile (64 x 32), transpose into As[k][row]
#pragma unroll
        for (int t = 0; t < 2; t++) {
            int i  = tid + t * 256;          // 0..511
            int r  = i >> 3;                 // 0..63
            int c4 = i & 7;                  // 0..7 (float4 within BK)
            int row = rowBase + r;
            float4 v = make_float4(0.f, 0.f, 0.f, 0.f);
            if (row < M) {
                v = *(const float4*)&A[(size_t)row * K + k0 + c4 * 4];
                if (ADD) {
                    float4 w = *(const float4*)&A2[(size_t)row * K + k0 + c4 * 4];
                    v.x += w.x; v.y += w.y; v.z += w.z; v.w += w.w;
                }
            }
            As[c4 * 4 + 0][r] = v.x;
            As[c4 * 4 + 1][r] = v.y;
            As[c4 * 4 + 2][r] = v.z;
            As[c4 * 4 + 3][r] = v.w;
        }
        // ---- load B tile (32 x 128)
#pragma unroll
        for (int t = 0; t < 4; t++) {
            int i  = tid + t * 256;          // 0..1023
            int r  = i >> 5;                 // 0..31
            int c4 = i & 31;                 // 0..31
            *(float4*)&Bs[r][c4 * 4] =
                *(const float4*)&W[(size_t)(k0 + r) * 128 + c4 * 4];
        }
        __syncthreads();

#pragma unroll
        for (int kk = 0; kk < BK; kk++) {
            float4 a0 = *(const float4*)&As[kk][trow * 8];
            float4 a1 = *(const float4*)&As[kk][trow * 8 + 4];
            float4 b  = *(const float4*)&Bs[kk][tcol * 4];
            float av[8] = {a0.x, a0.y, a0.z, a0.w, a1.x, a1.y, a1.z, a1.w};
            float bv[4] = {b.x, b.y, b.z, b.w};
#pragma unroll
            for (int i = 0; i < 8; i++)
#pragma unroll
                for (int j = 0; j < 4; j++)
                    acc[i][j] = fmaf(av[i], bv[j], acc[i][j]);
        }
        __syncthreads();
    }

    // ---- epilogue: bias (+relu), store
    float bv[4];
#pragma unroll
    for (int j = 0; j < 4; j++) bv[j] = bias[tcol * 4 + j];

#pragma unroll
    for (int i = 0; i < 8; i++) {
        int row = rowBase + trow * 8 + i;
        if (row < M) {
            float4 o;
            o.x = acc[i][0] + bv[0];
            o.y = acc[i][1] + bv[1];
            o.z = acc[i][2] + bv[2];
            o.w = acc[i][3] + bv[3];
            if (RELU) {
                o.x = fmaxf(o.x, 0.f); o.y = fmaxf(o.y, 0.f);
                o.z = fmaxf(o.z, 0.f); o.w = fmaxf(o.w, 0.f);
            }
            *(float4*)&out[(size_t)row * 128 + tcol * 4] = o;
        }
    }
}

// ---------------- zero a float buffer ----------------------------------------
__global__ void zero_k(float4* __restrict__ p, int n4)
{
    int i = blockIdx.x * blockDim.x + threadIdx.x;
    if (i < n4) p[i] = make_float4(0.f, 0.f, 0.f, 0.f);
}

// ---------------- edge scatter: agg[dst] += x[src] ----------------------------
// 32 threads (1 warp) per edge, float4 per lane -> 4 atomicAdds per lane.
__global__ void scatter_k(const float* __restrict__ x, const int* __restrict__ ei,
                          float* __restrict__ agg)
{
    int idx = blockIdx.x * blockDim.x + threadIdx.x;
    int e = idx >> 5;
    if (e >= EE) return;
    int l = idx & 31;
    int s = __ldg(&ei[e]);
    int d = __ldg(&ei[EE + e]);
    float4 v = *(const float4*)&x[(size_t)s * 128 + l * 4];
    float* a = &agg[(size_t)d * 128 + l * 4];
    atomicAdd(a + 0, v.x);
    atomicAdd(a + 1, v.y);
    atomicAdd(a + 2, v.z);
    atomicAdd(a + 3, v.w);
}

// ---------------- tail: z = x @ tail_W + tail_b (one warp per row) ------------
__global__ void tail_k(const float* __restrict__ x, const float* __restrict__ W,
                       const float* __restrict__ b, float* __restrict__ z)
{
    int idx = blockIdx.x * blockDim.x + threadIdx.x;
    int row = idx >> 5;
    if (row >= NN) return;
    int l = idx & 31;
    float4 xv = *(const float4*)&x[(size_t)row * 128 + l * 4];
    float4 wv = *(const float4*)&W[l * 4];
    float s = xv.x * wv.x + xv.y * wv.y + xv.z * wv.z + xv.w * wv.w;
#pragma unroll
    for (int o = 16; o; o >>= 1) s += __shfl_xor_sync(0xFFFFFFFFu, s, o);
    if (l == 0) z[row] = s + b[0];
}

// ---------------- BN stats: deterministic single-block two-pass ---------------
__global__ void stats_k(const float* __restrict__ z, float* __restrict__ stats)
{
    __shared__ float sh[1024];
    int tid = threadIdx.x;

    float s = 0.f;
    for (int i = tid; i < NN; i += 1024) s += z[i];
    sh[tid] = s;
    __syncthreads();
    for (int o = 512; o > 0; o >>= 1) {
        if (tid < o) sh[tid] += sh[tid + o];
        __syncthreads();
    }
    float mu = sh[0] / (float)NN;
    __syncthreads();

    float v = 0.f;
    for (int i = tid; i < NN; i += 1024) {
        float d = z[i] - mu;
        v += d * d;
    }
    sh[tid] = v;
    __syncthreads();
    for (int o = 512; o > 0; o >>= 1) {
        if (tid < o) sh[tid] += sh[tid + o];
        __syncthreads();
    }
    if (tid == 0) {
        stats[0] = mu;
        stats[1] = rsqrtf(sh[0] / (float)NN + 1e-5f);
    }
}

// ---------------- BN apply ----------------------------------------------------
__global__ void bn_k(const float* __restrict__ z, const float* __restrict__ stats,
                     const float* __restrict__ gamma, const float* __restrict__ beta,
                     float* __restrict__ out)
{
    int i = blockIdx.x * blockDim.x + threadIdx.x;
    if (i < NN) {
        out[i] = (z[i] - stats[0]) * stats[1] * gamma[0] + beta[0];
    }
}

// ---------------- launcher ----------------------------------------------------
extern "C" void kernel_launch(void* const* d_in, const int* in_sizes, int n_in,
                              void* d_out, int out_size)
{
    const float* feature = (const float*)d_in[0];
    const int*   ei      = (const int*)d_in[1];
    const float* head_W  = (const float*)d_in[2];
    const float* head_b  = (const float*)d_in[3];
    const float* gin_W1  = (const float*)d_in[4];
    const float* gin_b1  = (const float*)d_in[5];
    const float* lin_W1  = (const float*)d_in[6];
    const float* lin_b1  = (const float*)d_in[7];
    const float* gin_W2  = (const float*)d_in[8];
    const float* gin_b2  = (const float*)d_in[9];
    const float* lin_W2  = (const float*)d_in[10];
    const float* lin_b2  = (const float*)d_in[11];
    const float* tail_W  = (const float*)d_in[12];
    const float* tail_b  = (const float*)d_in[13];
    const float* bn_g    = (const float*)d_in[14];
    const float* bn_b    = (const float*)d_in[15];
    float* out = (float*)d_out;

    float *xp, *aggp, *hp, *zp, *stp;
    cudaGetSymbolAddress((void**)&xp,   g_x);
    cudaGetSymbolAddress((void**)&aggp, g_agg);
    cudaGetSymbolAddress((void**)&hp,   g_h);
    cudaGetSymbolAddress((void**)&zp,   g_z);
    cudaGetSymbolAddress((void**)&stp,  g_stats);

    const int gemmGrid = (NN + 63) / 64;            // 782
    const int zeroN4   = NN * DH / 4;               // 1.6M
    const int zeroGrid = (zeroN4 + 255) / 256;
    const int scatGrid = (EE * 32 + 255) / 256;     // 75000
    const int tailGrid = (NN * 32 + 255) / 256;
    const int bnGrid   = (NN + 255) / 256;

    // head: x = relu(feature @ head_W + head_b)
    gemm_k<true, false><<<gemmGrid, 256>>>(feature, nullptr, head_W, head_b, xp, NN, 512);

    // ---- GIN layer 1 ----
    zero_k<<<zeroGrid, 256>>>((float4*)aggp, zeroN4);
    scatter_k<<<scatGrid, 256>>>(xp, ei, aggp);
    gemm_k<true, true><<<gemmGrid, 256>>>(xp, aggp, gin_W1, gin_b1, hp, NN, 128);
    gemm_k<false, false><<<gemmGrid, 256>>>(hp, nullptr, lin_W1, lin_b1, xp, NN, 128);

    // ---- GIN layer 2 ----
    zero_k<<<zeroGrid, 256>>>((float4*)aggp, zeroN4);
    scatter_k<<<scatGrid, 256>>>(xp, ei, aggp);
    gemm_k<true, true><<<gemmGrid, 256>>>(xp, aggp, gin_W2, gin_b2, hp, NN, 128);
    gemm_k<false, false><<<gemmGrid, 256>>>(hp, nullptr, lin_W2, lin_b2, xp, NN, 128);

    // ---- tail + BN ----
    tail_k<<<tailGrid, 256>>>(xp, tail_W, tail_b, zp);
    stats_k<<<1, 1024>>>(zp, stp);
    bn_k<<<bnGrid, 256>>>(zp, stp, bn_g, bn_b, out);
}

// round 2
// speedup vs baseline: 1.3941x; 1.3941x over previous
#include <cuda_runtime.h>
#include <math.h>

// Problem constants (fixed by the reference)
#define NN 50000
#define DH 128
#define EE 600000

// ---------------- scratch (static device allocations) ------------------------
__device__ float g_x[NN * DH];       // node features after head / after each layer
__device__ float g_y[NN * DH];       // x[dst] + sum_neighbors (GIN pre-MLP input)
__device__ float g_h[NN * DH];       // GIN MLP hidden
__device__ float g_z[NN];            // tail output
__device__ float g_stats[2];         // mu, rstd
__device__ int   g_deg[NN];          // in-degree histogram
__device__ int   g_rowstart[NN + 1]; // CSR row offsets (by dst)
__device__ int   g_cursor[NN];       // fill cursors
__device__ int   g_adj[EE];          // src indices grouped by dst

// ---------------- GEMM: [M x K] * [K x 128] + bias (+relu) -------------------
// BM=64, BN=128, BK=32, 256 threads, each thread computes an 8x4 microtile.
template <bool RELU>
__global__ void __launch_bounds__(256, 2)
gemm_k(const float* __restrict__ A,
       const float* __restrict__ W, const float* __restrict__ bias,
       float* __restrict__ out, int M, int K)
{
    constexpr int BM = 64;
    constexpr int BK = 32;

    __shared__ float As[BK][BM + 4];
    __shared__ float Bs[BK][128];

    const int tid  = threadIdx.x;
    const int tcol = tid & 31;
    const int trow = tid >> 5;
    const int rowBase = blockIdx.x * BM;

    float acc[8][4];
#pragma unroll
    for (int i = 0; i < 8; i++)
#pragma unroll
        for (int j = 0; j < 4; j++) acc[i][j] = 0.f;

    for (int k0 = 0; k0 < K; k0 += BK) {
#pragma unroll
        for (int t = 0; t < 2; t++) {
            int i  = tid + t * 256;
            int r  = i >> 3;
            int c4 = i & 7;
            int row = rowBase + r;
            float4 v = make_float4(0.f, 0.f, 0.f, 0.f);
            if (row < M)
                v = *(const float4*)&A[(size_t)row * K + k0 + c4 * 4];
            As[c4 * 4 + 0][r] = v.x;
            As[c4 * 4 + 1][r] = v.y;
            As[c4 * 4 + 2][r] = v.z;
            As[c4 * 4 + 3][r] = v.w;
        }
#pragma unroll
        for (int t = 0; t < 4; t++) {
            int i  = tid + t * 256;
            int r  = i >> 5;
            int c4 = i & 31;
            *(float4*)&Bs[r][c4 * 4] =
                *(const float4*)&W[(size_t)(k0 + r) * 128 + c4 * 4];
        }
        __syncthreads();

#pragma unroll
        for (int kk = 0; kk < BK; kk++) {
            float4 a0 = *(const float4*)&As[kk][trow * 8];
            float4 a1 = *(const float4*)&As[kk][trow * 8 + 4];
            float4 b  = *(const float4*)&Bs[kk][tcol * 4];
            float av[8] = {a0.x, a0.y, a0.z, a0.w, a1.x, a1.y, a1.z, a1.w};
            float bv[4] = {b.x, b.y, b.z, b.w};
#pragma unroll
            for (int i = 0; i < 8; i++)
#pragma unroll
                for (int j = 0; j < 4; j++)
                    acc[i][j] = fmaf(av[i], bv[j], acc[i][j]);
        }
        __syncthreads();
    }

    float bv[4];
#pragma unroll
    for (int j = 0; j < 4; j++) bv[j] = bias[tcol * 4 + j];

#pragma unroll
    for (int i = 0; i < 8; i++) {
        int row = rowBase + trow * 8 + i;
        if (row < M) {
            float4 o;
            o.x = acc[i][0] + bv[0];
            o.y = acc[i][1] + bv[1];
            o.z = acc[i][2] + bv[2];
            o.w = acc[i][3] + bv[3];
            if (RELU) {
                o.x = fmaxf(o.x, 0.f); o.y = fmaxf(o.y, 0.f);
                o.z = fmaxf(o.z, 0.f); o.w = fmaxf(o.w, 0.f);
            }
            *(float4*)&out[(size_t)row * 128 + tcol * 4] = o;
        }
    }
}

// ---------------- CSR build ---------------------------------------------------
__global__ void zero_deg_k(int* __restrict__ deg)
{
    int i = blockIdx.x * blockDim.x + threadIdx.x;
    if (i < NN) deg[i] = 0;
}

__global__ void degree_k(const int* __restrict__ ei, int* __restrict__ deg)
{
    int e = blockIdx.x * blockDim.x + threadIdx.x;
    if (e < EE) atomicAdd(&deg[ei[EE + e]], 1);
}

// Single-block chunked exclusive scan over NN degrees -> rowstart, cursor.
__global__ void scan_k(const int* __restrict__ deg, int* __restrict__ rowstart,
                       int* __restrict__ cursor)
{
    __shared__ int sh[1024];
    const int tid = threadIdx.x;
    const int CH  = (NN + 1023) / 1024;   // 49
    const int base = tid * CH;

    int s = 0;
    for (int i = 0; i < CH; i++) {
        int idx = base + i;
        if (idx < NN) s += deg[idx];
    }
    sh[tid] = s;
    __syncthreads();
    // Hillis-Steele inclusive scan
    for (int o = 1; o < 1024; o <<= 1) {
        int v = (tid >= o) ? sh[tid - o] : 0;
        __syncthreads();
        sh[tid] += v;
        __syncthreads();
    }
    int run = sh[tid] - s;   // exclusive prefix for this chunk
    for (int i = 0; i < CH; i++) {
        int idx = base + i;
        if (idx < NN) {
            rowstart[idx] = run;
            cursor[idx]   = run;
            run += deg[idx];
        }
    }
    if (tid == 1023) rowstart[NN] = sh[1023];
}

__global__ void fill_k(const int* __restrict__ ei, int* __restrict__ cursor,
                       int* __restrict__ adj)
{
    int e = blockIdx.x * blockDim.x + threadIdx.x;
    if (e < EE) {
        int s = ei[e];
        int d = ei[EE + e];
        int p = atomicAdd(&cursor[d], 1);
        adj[p] = s;
    }
}

// ---------------- aggregation gather: y[n] = x[n] + sum_{s in N(n)} x[s] ------
// One warp per node; each lane owns 4 feature columns (float4).
__global__ void gather_k(const float* __restrict__ x,
                         const int* __restrict__ rowstart,
                         const int* __restrict__ adj,
                         float* __restrict__ y)
{
    int idx = blockIdx.x * blockDim.x + threadIdx.x;
    int n = idx >> 5;
    if (n >= NN) return;
    int l = idx & 31;

    float4 acc = *(const float4*)&x[(size_t)n * 128 + l * 4];
    int start = __ldg(&rowstart[n]);
    int end   = __ldg(&rowstart[n + 1]);
    for (int j = start; j < end; j++) {
        int s = __ldg(&adj[j]);             // warp-uniform broadcast load
        float4 v = *(const float4*)&x[(size_t)s * 128 + l * 4];
        acc.x += v.x; acc.y += v.y; acc.z += v.z; acc.w += v.w;
    }
    *(float4*)&y[(size_t)n * 128 + l * 4] = acc;
}

// ---------------- tail: z = x @ tail_W + tail_b (one warp per row) ------------
__global__ void tail_k(const float* __restrict__ x, const float* __restrict__ W,
                       const float* __restrict__ b, float* __restrict__ z)
{
    int idx = blockIdx.x * blockDim.x + threadIdx.x;
    int row = idx >> 5;
    if (row >= NN) return;
    int l = idx & 31;
    float4 xv = *(const float4*)&x[(size_t)row * 128 + l * 4];
    float4 wv = *(const float4*)&W[l * 4];
    float s = xv.x * wv.x + xv.y * wv.y + xv.z * wv.z + xv.w * wv.w;
#pragma unroll
    for (int o = 16; o; o >>= 1) s += __shfl_xor_sync(0xFFFFFFFFu, s, o);
    if (l == 0) z[row] = s + b[0];
}

// ---------------- BN stats: deterministic single-block two-pass ---------------
__global__ void stats_k(const float* __restrict__ z, float* __restrict__ stats)
{
    __shared__ float sh[1024];
    int tid = threadIdx.x;

    float s = 0.f;
    for (int i = tid; i < NN; i += 1024) s += z[i];
    sh[tid] = s;
    __syncthreads();
    for (int o = 512; o > 0; o >>= 1) {
        if (tid < o) sh[tid] += sh[tid + o];
        __syncthreads();
    }
    float mu = sh[0] / (float)NN;
    __syncthreads();

    float v = 0.f;
    for (int i = tid; i < NN; i += 1024) {
        float d = z[i] - mu;
        v += d * d;
    }
    sh[tid] = v;
    __syncthreads();
    for (int o = 512; o > 0; o >>= 1) {
        if (tid < o) sh[tid] += sh[tid + o];
        __syncthreads();
    }
    if (tid == 0) {
        stats[0] = mu;
        stats[1] = rsqrtf(sh[0] / (float)NN + 1e-5f);
    }
}

// ---------------- BN apply ----------------------------------------------------
__global__ void bn_k(const float* __restrict__ z, const float* __restrict__ stats,
                     const float* __restrict__ gamma, const float* __restrict__ beta,
                     float* __restrict__ out)
{
    int i = blockIdx.x * blockDim.x + threadIdx.x;
    if (i < NN) {
        out[i] = (z[i] - stats[0]) * stats[1] * gamma[0] + beta[0];
    }
}

// ---------------- launcher ----------------------------------------------------
extern "C" void kernel_launch(void* const* d_in, const int* in_sizes, int n_in,
                              void* d_out, int out_size)
{
    const float* feature = (const float*)d_in[0];
    const int*   ei      = (const int*)d_in[1];
    const float* head_W  = (const float*)d_in[2];
    const float* head_b  = (const float*)d_in[3];
    const float* gin_W1  = (const float*)d_in[4];
    const float* gin_b1  = (const float*)d_in[5];
    const float* lin_W1  = (const float*)d_in[6];
    const float* lin_b1  = (const float*)d_in[7];
    const float* gin_W2  = (const float*)d_in[8];
    const float* gin_b2  = (const float*)d_in[9];
    const float* lin_W2  = (const float*)d_in[10];
    const float* lin_b2  = (const float*)d_in[11];
    const float* tail_W  = (const float*)d_in[12];
    const float* tail_b  = (const float*)d_in[13];
    const float* bn_g    = (const float*)d_in[14];
    const float* bn_b    = (const float*)d_in[15];
    float* out = (float*)d_out;

    float *xp, *yp, *hp, *zp, *stp;
    int *degp, *rsp, *curp, *adjp;
    cudaGetSymbolAddress((void**)&xp,   g_x);
    cudaGetSymbolAddress((void**)&yp,   g_y);
    cudaGetSymbolAddress((void**)&hp,   g_h);
    cudaGetSymbolAddress((void**)&zp,   g_z);
    cudaGetSymbolAddress((void**)&stp,  g_stats);
    cudaGetSymbolAddress((void**)&degp, g_deg);
    cudaGetSymbolAddress((void**)&rsp,  g_rowstart);
    cudaGetSymbolAddress((void**)&curp, g_cursor);
    cudaGetSymbolAddress((void**)&adjp, g_adj);

    const int gemmGrid  = (NN + 63) / 64;          // 782
    const int edgeGrid  = (EE + 255) / 256;
    const int nodeGrid  = (NN + 255) / 256;
    const int warpGrid  = (NN * 32 + 255) / 256;   // warp-per-node kernels

    // ---- CSR build (once; reused by both layers) ----
    zero_deg_k<<<nodeGrid, 256>>>(degp);
    degree_k<<<edgeGrid, 256>>>(ei, degp);
    scan_k<<<1, 1024>>>(degp, rsp, curp);
    fill_k<<<edgeGrid, 256>>>(ei, curp, adjp);

    // head: x = relu(feature @ head_W + head_b)   (overlaps CSR build)
    gemm_k<true><<<gemmGrid, 256>>>(feature, head_W, head_b, xp, NN, 512);

    // ---- GIN layer 1 ----
    gather_k<<<warpGrid, 256>>>(xp, rsp, adjp, yp);
    gemm_k<true><<<gemmGrid, 256>>>(yp, gin_W1, gin_b1, hp, NN, 128);
    gemm_k<false><<<gemmGrid, 256>>>(hp, lin_W1, lin_b1, xp, NN, 128);

    // ---- GIN layer 2 ----
    gather_k<<<warpGrid, 256>>>(xp, rsp, adjp, yp);
    gemm_k<true><<<gemmGrid, 256>>>(yp, gin_W2, gin_b2, hp, NN, 128);
    gemm_k<false><<<gemmGrid, 256>>>(hp, lin_W2, lin_b2, xp, NN, 128);

    // ---- tail + BN ----
    tail_k<<<warpGrid, 256>>>(xp, tail_W, tail_b, zp);
    stats_k<<<1, 1024>>>(zp, stp);
    bn_k<<<nodeGrid, 256>>>(zp, stp, bn_g, bn_b, out);
}

// round 4
// speedup vs baseline: 1.4874x; 1.0669x over previous
#include <cuda_runtime.h>
#include <cuda_bf16.h>
#include <math.h>
#include <cstdint>

// Problem constants
#define NN 50000
#define DH 128
#define EE 600000

// ---------------- scratch ------------------------------------------------------
__device__ float g_x[NN * DH];
__device__ float g_y[NN * DH];
__device__ float g_h[NN * DH];
__device__ float g_z[NN];
__device__ float g_stats[2];
__device__ int   g_deg[NN];
__device__ int   g_rowstart[NN + 1];
__device__ int   g_cursor[NN];
__device__ int   g_adj[EE];

// ---------------- helpers ------------------------------------------------------
__device__ __forceinline__ uint32_t smem_u32(const void* p) {
    uint32_t a;
    asm("{ .reg .u64 t; cvta.to.shared.u64 t, %1; cvt.u32.u64 %0, t; }" : "=r"(a) : "l"(p));
    return a;
}

__device__ __forceinline__ void ldsm_x4(uint32_t* r, uint32_t addr) {
    asm volatile("ldmatrix.sync.aligned.m8n8.x4.shared.b16 {%0,%1,%2,%3}, [%4];"
                 : "=r"(r[0]), "=r"(r[1]), "=r"(r[2]), "=r"(r[3]) : "r"(addr));
}
__device__ __forceinline__ void ldsm_x4_t(uint32_t* r, uint32_t addr) {
    asm volatile("ldmatrix.sync.aligned.m8n8.x4.trans.shared.b16 {%0,%1,%2,%3}, [%4];"
                 : "=r"(r[0]), "=r"(r[1]), "=r"(r[2]), "=r"(r[3]) : "r"(addr));
}
__device__ __forceinline__ void mma16816(float* d, const uint32_t* a, const uint32_t* b) {
    asm volatile(
        "mma.sync.aligned.m16n8k16.row.col.f32.bf16.bf16.f32 "
        "{%0,%1,%2,%3}, {%4,%5,%6,%7}, {%8,%9}, {%0,%1,%2,%3};"
        : "+f"(d[0]), "+f"(d[1]), "+f"(d[2]), "+f"(d[3])
        : "r"(a[0]), "r"(a[1]), "r"(a[2]), "r"(a[3]), "r"(b[0]), "r"(b[1]));
}
__device__ __forceinline__ uint32_t pack2(__nv_bfloat16 x, __nv_bfloat16 y) {
    __nv_bfloat162 t(x, y);
    return *(uint32_t*)&t;
}

// smem layout offsets (bytes). A tiles: 64 rows x 128 k bf16 (256B rows).
// B tiles: 128 k x 128 n bf16 (256B rows).
static constexpr int OA_HI = 0;
static constexpr int OA_LO = 16384;
static constexpr int OB_HI = 32768;
static constexpr int OB_LO = 65536;
static constexpr int SMEM_GEMM = 98304;

// swizzled byte offset inside a 256B-row tile (row-major, 2B elems)
__device__ __forceinline__ uint32_t sw_off(int row, int col) {
    return (uint32_t)row * 256u + (((uint32_t)col * 2u) ^ (((uint32_t)row & 7u) << 4));
}

// ---------------- HMMA GEMM: out[M,128] = A[M,K]@W[K,128] + bias (+relu) -------
// fp32 via bf16 hi/lo split: D = Ah*Bh + Ah*Bl + Al*Bh.
template <bool RELU>
__global__ void __launch_bounds__(256, 2)
mma_gemm(const float* __restrict__ A, const float* __restrict__ W,
         const float* __restrict__ bias, float* __restrict__ out, int M, int K)
{
    extern __shared__ char smem[];
    const uint32_t sb = smem_u32(smem);
    const int tid  = threadIdx.x;
    const int wid  = tid >> 5;
    const int lane = tid & 31;
    const int wm = wid & 1;          // 2 m-slabs of 32 rows
    const int wn = wid >> 1;         // 4 n-slabs of 32 cols
    const int rowBase = blockIdx.x * 64;

    float acc[2][4][4];
#pragma unroll
    for (int i = 0; i < 2; i++)
#pragma unroll
        for (int j = 0; j < 4; j++)
#pragma unroll
            for (int q = 0; q < 4; q++) acc[i][j][q] = 0.f;

    const int grp = lane >> 3;
    const int li  = lane & 7;

    const int nchunk = K >> 7;
    for (int c = 0; c < nchunk; c++) {
        __syncthreads();
        // ---- fill A: 64 rows x 128 k, hi/lo bf16, swizzled
#pragma unroll
        for (int t = 0; t < 8; t++) {
            int slot = tid + t * 256;        // 0..2047 float4 slots
            int r  = slot >> 5;              // 0..63
            int k4 = (slot & 31) * 4;
            int grow = rowBase + r;
            float4 v = make_float4(0.f, 0.f, 0.f, 0.f);
            if (grow < M)
                v = *(const float4*)&A[(size_t)grow * K + c * 128 + k4];
            __nv_bfloat16 h0 = __float2bfloat16(v.x), h1 = __float2bfloat16(v.y);
            __nv_bfloat16 h2 = __float2bfloat16(v.z), h3 = __float2bfloat16(v.w);
            float l0 = v.x - __bfloat162float(h0), l1 = v.y - __bfloat162float(h1);
            float l2 = v.z - __bfloat162float(h2), l3 = v.w - __bfloat162float(h3);
            uint32_t o = sw_off(r, k4);
            *(uint32_t*)(smem + OA_HI + o)     = pack2(h0, h1);
            *(uint32_t*)(smem + OA_HI + o + 4) = pack2(h2, h3);
            *(uint32_t*)(smem + OA_LO + o)     = pack2(__float2bfloat16(l0), __float2bfloat16(l1));
            *(uint32_t*)(smem + OA_LO + o + 4) = pack2(__float2bfloat16(l2), __float2bfloat16(l3));
        }
        // ---- fill B: 128 k x 128 n (direct copy of W slice), hi/lo, swizzled
#pragma unroll
        for (int t = 0; t < 16; t++) {
            int slot = tid + t * 256;        // 0..4095 float4 slots
            int k  = slot >> 5;              // 0..127
            int n4 = (slot & 31) * 4;
            float4 v = *(const float4*)&W[(size_t)(c * 128 + k) * 128 + n4];
            __nv_bfloat16 h0 = __float2bfloat16(v.x), h1 = __float2bfloat16(v.y);
            __nv_bfloat16 h2 = __float2bfloat16(v.z), h3 = __float2bfloat16(v.w);
            float l0 = v.x - __bfloat162float(h0), l1 = v.y - __bfloat162float(h1);
            float l2 = v.z - __bfloat162float(h2), l3 = v.w - __bfloat162float(h3);
            uint32_t o = sw_off(k, n4);
            *(uint32_t*)(smem + OB_HI + o)     = pack2(h0, h1);
            *(uint32_t*)(smem + OB_HI + o + 4) = pack2(h2, h3);
            *(uint32_t*)(smem + OB_LO + o)     = pack2(__float2bfloat16(l0), __float2bfloat16(l1));
            *(uint32_t*)(smem + OB_LO + o + 4) = pack2(__float2bfloat16(l2), __float2bfloat16(l3));
        }
        __syncthreads();

        // ---- 8 k-steps of 16
#pragma unroll
        for (int ks = 0; ks < 8; ks++) {
            int k0 = ks * 16;
            uint32_t ah[2][4], al[2][4];
#pragma unroll
            for (int mt = 0; mt < 2; mt++) {
                int r = wm * 32 + mt * 16 + li + (grp & 1) * 8;
                int kk = k0 + (grp >> 1) * 8;
                uint32_t addr = sb + OA_HI + sw_off(r, kk);
                ldsm_x4(ah[mt], addr);
                ldsm_x4(al[mt], addr + (OA_LO - OA_HI));
            }
            uint32_t bh[4][2], bl[4][2];
#pragma unroll
            for (int ntp = 0; ntp < 2; ntp++) {
                int kk = k0 + li + (grp & 1) * 8;
                int n  = wn * 32 + ntp * 16 + (grp >> 1) * 8;
                uint32_t addr = sb + OB_HI + sw_off(kk, n);
                uint32_t r4[4];
                ldsm_x4_t(r4, addr);
                bh[ntp * 2][0] = r4[0]; bh[ntp * 2][1] = r4[1];
                bh[ntp * 2 + 1][0] = r4[2]; bh[ntp * 2 + 1][1] = r4[3];
                ldsm_x4_t(r4, addr + (OB_LO - OB_HI));
                bl[ntp * 2][0] = r4[0]; bl[ntp * 2][1] = r4[1];
                bl[ntp * 2 + 1][0] = r4[2]; bl[ntp * 2 + 1][1] = r4[3];
            }
#pragma unroll
            for (int mt = 0; mt < 2; mt++)
#pragma unroll
                for (int nt = 0; nt < 4; nt++)
                    mma16816(acc[mt][nt], ah[mt], bh[nt]);
#pragma unroll
            for (int mt = 0; mt < 2; mt++)
#pragma unroll
                for (int nt = 0; nt < 4; nt++)
                    mma16816(acc[mt][nt], ah[mt], bl[nt]);
#pragma unroll
            for (int mt = 0; mt < 2; mt++)
#pragma unroll
                for (int nt = 0; nt < 4; nt++)
                    mma16816(acc[mt][nt], al[mt], bh[nt]);
        }
    }

    // ---- epilogue: bias (+relu), store
#pragma unroll
    for (int mt = 0; mt < 2; mt++) {
#pragma unroll
        for (int nt = 0; nt < 4; nt++) {
            int r0 = rowBase + wm * 32 + mt * 16 + (lane >> 2);
            int cc = wn * 32 + nt * 8 + (lane & 3) * 2;
            float b0 = __ldg(&bias[cc]);
            float b1 = __ldg(&bias[cc + 1]);
            float v0 = acc[mt][nt][0] + b0, v1 = acc[mt][nt][1] + b1;
            float v2 = acc[mt][nt][2] + b0, v3 = acc[mt][nt][3] + b1;
            if (RELU) {
                v0 = fmaxf(v0, 0.f); v1 = fmaxf(v1, 0.f);
                v2 = fmaxf(v2, 0.f); v3 = fmaxf(v3, 0.f);
            }
            if (r0 < M)     *(float2*)&out[(size_t)r0 * 128 + cc]       = make_float2(v0, v1);
            if (r0 + 8 < M) *(float2*)&out[(size_t)(r0 + 8) * 128 + cc] = make_float2(v2, v3);
        }
    }
}

// ---------------- CSR build ---------------------------------------------------
__global__ void zero_deg_k(int* __restrict__ deg)
{
    int i = blockIdx.x * blockDim.x + threadIdx.x;
    if (i < NN) deg[i] = 0;
}
__global__ void degree_k(const int* __restrict__ ei, int* __restrict__ deg)
{
    int e = blockIdx.x * blockDim.x + threadIdx.x;
    if (e < EE) atomicAdd(&deg[ei[EE + e]], 1);
}
__global__ void scan_k(const int* __restrict__ deg, int* __restrict__ rowstart,
                       int* __restrict__ cursor)
{
    __shared__ int sh[1024];
    const int tid = threadIdx.x;
    const int CH  = (NN + 1023) / 1024;
    const int base = tid * CH;

    int s = 0;
    for (int i = 0; i < CH; i++) {
        int idx = base + i;
        if (idx < NN) s += deg[idx];
    }
    sh[tid] = s;
    __syncthreads();
    for (int o = 1; o < 1024; o <<= 1) {
        int v = (tid >= o) ? sh[tid - o] : 0;
        __syncthreads();
        sh[tid] += v;
        __syncthreads();
    }
    int run = sh[tid] - s;
    for (int i = 0; i < CH; i++) {
        int idx = base + i;
        if (idx < NN) {
            rowstart[idx] = run;
            cursor[idx]   = run;
            run += deg[idx];
        }
    }
    if (tid == 1023) rowstart[NN] = sh[1023];
}
__global__ void fill_k(const int* __restrict__ ei, int* __restrict__ cursor,
                       int* __restrict__ adj)
{
    int e = blockIdx.x * blockDim.x + threadIdx.x;
    if (e < EE) {
        int s = ei[e];
        int d = ei[EE + e];
        int p = atomicAdd(&cursor[d], 1);
        adj[p] = s;
    }
}

// ---------------- gather: y[n] = x[n] + sum_{s in N(n)} x[s] ------------------
__global__ void gather_k(const float* __restrict__ x,
                         const int* __restrict__ rowstart,
                         const int* __restrict__ adj,
                         float* __restrict__ y)
{
    int idx = blockIdx.x * blockDim.x + threadIdx.x;
    int n = idx >> 5;
    if (n >= NN) return;
    int l = idx & 31;

    float4 acc = *(const float4*)&x[(size_t)n * 128 + l * 4];
    int start = __ldg(&rowstart[n]);
    int end   = __ldg(&rowstart[n + 1]);
    for (int j = start; j < end; j++) {
        int s = __ldg(&adj[j]);
        float4 v = *(const float4*)&x[(size_t)s * 128 + l * 4];
        acc.x += v.x; acc.y += v.y; acc.z += v.z; acc.w += v.w;
    }
    *(float4*)&y[(size_t)n * 128 + l * 4] = acc;
}

// ---------------- tail ---------------------------------------------------------
__global__ void tail_k(const float* __restrict__ x, const float* __restrict__ W,
                       const float* __restrict__ b, float* __restrict__ z)
{
    int idx = blockIdx.x * blockDim.x + threadIdx.x;
    int row = idx >> 5;
    if (row >= NN) return;
    int l = idx & 31;
    float4 xv = *(const float4*)&x[(size_t)row * 128 + l * 4];
    float4 wv = *(const float4*)&W[l * 4];
    float s = xv.x * wv.x + xv.y * wv.y + xv.z * wv.z + xv.w * wv.w;
#pragma unroll
    for (int o = 16; o; o >>= 1) s += __shfl_xor_sync(0xFFFFFFFFu, s, o);
    if (l == 0) z[row] = s + b[0];
}

// ---------------- BN -----------------------------------------------------------
__global__ void stats_k(const float* __restrict__ z, float* __restrict__ stats)
{
    __shared__ float sh[1024];
    int tid = threadIdx.x;

    float s = 0.f;
    for (int i = tid; i < NN; i += 1024) s += z[i];
    sh[tid] = s;
    __syncthreads();
    for (int o = 512; o > 0; o >>= 1) {
        if (tid < o) sh[tid] += sh[tid + o];
        __syncthreads();
    }
    float mu = sh[0] / (float)NN;
    __syncthreads();

    float v = 0.f;
    for (int i = tid; i < NN; i += 1024) {
        float d = z[i] - mu;
        v += d * d;
    }
    sh[tid] = v;
    __syncthreads();
    for (int o = 512; o > 0; o >>= 1) {
        if (tid < o) sh[tid] += sh[tid + o];
        __syncthreads();
    }
    if (tid == 0) {
        stats[0] = mu;
        stats[1] = rsqrtf(sh[0] / (float)NN + 1e-5f);
    }
}
__global__ void bn_k(const float* __restrict__ z, const float* __restrict__ stats,
                     const float* __restrict__ gamma, const float* __restrict__ beta,
                     float* __restrict__ out)
{
    int i = blockIdx.x * blockDim.x + threadIdx.x;
    if (i < NN) {
        out[i] = (z[i] - stats[0]) * stats[1] * gamma[0] + beta[0];
    }
}

// ---------------- launcher ------------------------------------------------------
extern "C" void kernel_launch(void* const* d_in, const int* in_sizes, int n_in,
                              void* d_out, int out_size)
{
    const float* feature = (const float*)d_in[0];
    const int*   ei      = (const int*)d_in[1];
    const float* head_W  = (const float*)d_in[2];
    const float* head_b  = (const float*)d_in[3];
    const float* gin_W1  = (const float*)d_in[4];
    const float* gin_b1  = (const float*)d_in[5];
    const float* lin_W1  = (const float*)d_in[6];
    const float* lin_b1  = (const float*)d_in[7];
    const float* gin_W2  = (const float*)d_in[8];
    const float* gin_b2  = (const float*)d_in[9];
    const float* lin_W2  = (const float*)d_in[10];
    const float* lin_b2  = (const float*)d_in[11];
    const float* tail_W  = (const float*)d_in[12];
    const float* tail_b  = (const float*)d_in[13];
    const float* bn_g    = (const float*)d_in[14];
    const float* bn_b    = (const float*)d_in[15];
    float* out = (float*)d_out;

    float *xp, *yp, *hp, *zp, *stp;
    int *degp, *rsp, *curp, *adjp;
    cudaGetSymbolAddress((void**)&xp,   g_x);
    cudaGetSymbolAddress((void**)&yp,   g_y);
    cudaGetSymbolAddress((void**)&hp,   g_h);
    cudaGetSymbolAddress((void**)&zp,   g_z);
    cudaGetSymbolAddress((void**)&stp,  g_stats);
    cudaGetSymbolAddress((void**)&degp, g_deg);
    cudaGetSymbolAddress((void**)&rsp,  g_rowstart);
    cudaGetSymbolAddress((void**)&curp, g_cursor);
    cudaGetSymbolAddress((void**)&adjp, g_adj);

    static bool attr_done = false;
    if (!attr_done) {
        cudaFuncSetAttribute(mma_gemm<true>,  cudaFuncAttributeMaxDynamicSharedMemorySize, SMEM_GEMM);
        cudaFuncSetAttribute(mma_gemm<false>, cudaFuncAttributeMaxDynamicSharedMemorySize, SMEM_GEMM);
        attr_done = true;
    }

    const int gemmGrid = (NN + 63) / 64;           // 782
    const int edgeGrid = (EE + 255) / 256;
    const int nodeGrid = (NN + 255) / 256;
    const int warpGrid = (NN * 32 + 255) / 256;

    // ---- CSR build (once per call) ----
    zero_deg_k<<<nodeGrid, 256>>>(degp);
    degree_k<<<edgeGrid, 256>>>(ei, degp);
    scan_k<<<1, 1024>>>(degp, rsp, curp);
    fill_k<<<edgeGrid, 256>>>(ei, curp, adjp);

    // head
    mma_gemm<true><<<gemmGrid, 256, SMEM_GEMM>>>(feature, head_W, head_b, xp, NN, 512);

    // GIN layer 1
    gather_k<<<warpGrid, 256>>>(xp, rsp, adjp, yp);
    mma_gemm<true><<<gemmGrid, 256, SMEM_GEMM>>>(yp, gin_W1, gin_b1, hp, NN, 128);
    mma_gemm<false><<<gemmGrid, 256, SMEM_GEMM>>>(hp, lin_W1, lin_b1, xp, NN, 128);

    // GIN layer 2
    gather_k<<<warpGrid, 256>>>(xp, rsp, adjp, yp);
    mma_gemm<true><<<gemmGrid, 256, SMEM_GEMM>>>(yp, gin_W2, gin_b2, hp, NN, 128);
    mma_gemm<false><<<gemmGrid, 256, SMEM_GEMM>>>(hp, lin_W2, lin_b2, xp, NN, 128);

    // tail + BN
    tail_k<<<warpGrid, 256>>>(xp, tail_W, tail_b, zp);
    stats_k<<<1, 1024>>>(zp, stp);
    bn_k<<<nodeGrid, 256>>>(zp, stp, bn_g, bn_b, out);
}